// round 12
// baseline (speedup 1.0000x reference)
#include <cuda_runtime.h>
#include <cuda_bf16.h>
#include <math.h>

// Problem constants
#define T_LEN  4096
#define C_CH   64
#define B_SZ   64
#define NFREQ  2049            // T/2 + 1
#define FPAD   2052            // padded row for alignment
#define NCAND  6               // 2 * TOP_K
#define TOPK   3
#define NGRP   8               // channel-pair groups per batch (4 pairs each)

// Bank-conflict-killing smem swizzle for float2 z[4096]
#define SWZ(i) ((i) ^ (((i) >> 4) & 15))

// ---------------------------------------------------------------------------
// Scratch (device globals; no allocations allowed)
// ---------------------------------------------------------------------------
__device__ float2 g_xc [B_SZ * 32 * T_LEN];  // packed transpose: (x[t,2p], x[t,2p+1])
__device__ float  g_part[B_SZ * NGRP * FPAD];// per-(batch, pair-group) amplitude sums
__device__ float  g_amps[B_SZ * FPAD];       // reduced amplitudes per batch
__device__ int    g_topidx[B_SZ * NCAND];    // top-6 frequency indices per batch
__device__ float  g_scores[B_SZ * NCAND];    // autocorr scores per candidate
__device__ float  g_q [B_SZ * T_LEN];        // ||x[b,t]||^2
__device__ float  g_r [B_SZ * NCAND * T_LEN];// <x[b,t], x[b,t+p_j]>

__device__ __forceinline__ float2 cmul(float2 a, float2 b) {
    return make_float2(a.x * b.x - a.y * b.y, a.x * b.y + a.y * b.x);
}

__device__ __forceinline__ int cand_period(int idx) {
    const float pf = 4096.0f / (float)(idx + 1);
    int p = (int)floorf(pf);
    return min(max(p, 2), T_LEN / 2);
}

// argmax combine: higher value wins; tie -> smaller index
__device__ __forceinline__ void argmax2(float& v, int& i, float v2, int i2) {
    if (v2 > v || (v2 == v && i2 < i)) { v = v2; i = i2; }
}

// ---------------------------------------------------------------------------
// Kernel 0: transpose/pack x[b,t,c] -> xc[b, c/2, t] as float2 AND compute
// q[b][t] = ||x[b,t]||^2 on the fly. grid = (T/64, B), 256 threads.
// ---------------------------------------------------------------------------
__global__ __launch_bounds__(256) void transpose_kernel(const float* __restrict__ x)
{
    __shared__ float tile[64][68];       // 64 t-rows x 64 channels, pad 68 (f4-aligned)

    const int b   = blockIdx.y;
    const int t0  = blockIdx.x * 64;
    const int tid = threadIdx.x;

    // Load: thread handles row r = tid/4, 16 floats starting at (tid%4)*16.
    {
        const int r  = tid >> 2;
        const int c0 = (tid & 3) * 16;
        const float* src = x + (size_t)b * T_LEN * C_CH + (size_t)(t0 + r) * C_CH + c0;
        float qp = 0.0f;
        #pragma unroll
        for (int i = 0; i < 4; i++) {
            const float4 v = *(const float4*)(src + 4 * i);
            *(float4*)&tile[r][c0 + 4 * i] = v;
            qp += v.x * v.x + v.y * v.y + v.z * v.z + v.w * v.w;
        }
        // reduce across the 4 threads covering this row (lanes 4k..4k+3)
        qp += __shfl_down_sync(0xffffffffu, qp, 2, 4);
        qp += __shfl_down_sync(0xffffffffu, qp, 1, 4);
        if ((tid & 3) == 0)
            g_q[b * T_LEN + t0 + r] = qp;
    }
    __syncthreads();

    // Store: warp w covers pairs 4w..4w+3; 8-lane group per pair, consecutive t.
    {
        const int lane = tid & 31;
        const int warp = tid >> 5;
        const int p    = warp * 4 + (lane >> 3);   // 0..31
        const int tloc = lane & 7;
        float2* dst = g_xc + ((size_t)b * 32 + p) * T_LEN + t0;
        #pragma unroll
        for (int i = 0; i < 8; i++) {
            const int t = tloc + 8 * i;
            dst[t] = *(const float2*)&tile[t][2 * p];
        }
    }
}

// DFT-4 in place: (a,b,c,d) -> (X0,X1,X2,X3), W4 = exp(-2*pi*i/4) = -i
__device__ __forceinline__ void dft4(float2& a, float2& b, float2& c, float2& d)
{
    const float2 s02 = make_float2(a.x + c.x, a.y + c.y);
    const float2 d02 = make_float2(a.x - c.x, a.y - c.y);
    const float2 s13 = make_float2(b.x + d.x, b.y + d.y);
    const float2 d13 = make_float2(b.x - d.x, b.y - d.y);
    a = make_float2(s02.x + s13.x, s02.y + s13.y);
    b = make_float2(d02.x + d13.y, d02.y - d13.x);   // d02 - i*d13
    c = make_float2(s02.x - s13.x, s02.y - s13.y);
    d = make_float2(d02.x - d13.y, d02.y + d13.x);   // d02 + i*d13
}

// In-place DFT-16. Input natural order v[0..15]; output X[k1+4k2] lives in
// v[4k1+k2] (use PREG to fetch X[r]).
#define PREG(r) (4 * ((r) & 3) + ((r) >> 2))
__device__ __forceinline__ void dft16(float2 v[16])
{
    const float C1 = 0.92387953251128674f;   // cos(pi/8)
    const float S1 = 0.38268343236508978f;   // sin(pi/8)
    const float C2 = 0.70710678118654752f;   // cos(pi/4)

    #pragma unroll
    for (int t2 = 0; t2 < 4; t2++)
        dft4(v[t2], v[4 + t2], v[8 + t2], v[12 + t2]);

    v[5]  = cmul(v[5],  make_float2( C1, -S1));  // W^1
    v[6]  = cmul(v[6],  make_float2( C2, -C2));  // W^2
    v[7]  = cmul(v[7],  make_float2( S1, -C1));  // W^3
    v[9]  = cmul(v[9],  make_float2( C2, -C2));  // W^2
    v[10] = make_float2(v[10].y, -v[10].x);      // W^4 = -i
    v[11] = cmul(v[11], make_float2(-C2, -C2));  // W^6
    v[13] = cmul(v[13], make_float2( S1, -C1));  // W^3
    v[14] = cmul(v[14], make_float2(-C2, -C2));  // W^6
    v[15] = cmul(v[15], make_float2(-C1,  S1));  // W^9

    #pragma unroll
    for (int k1 = 0; k1 < 4; k1++)
        dft4(v[4 * k1], v[4 * k1 + 1], v[4 * k1 + 2], v[4 * k1 + 3]);
}

// Apply step twiddles v[r] *= exp(-2*pi*i*m*r/(16*Ns)) via cumulative products
__device__ __forceinline__ void step_twiddle(float2 v[16], int m, float invNs16)
{
    const float ang = -6.283185307179586f * (float)m * invNs16;
    float s, c;
    sincosf(ang, &s, &c);
    const float2 w1 = make_float2(c, s);
    float2 w = w1;
    #pragma unroll
    for (int r = 1; r < 16; r++) {
        v[r] = cmul(v[r], w);
        if (r < 15) w = cmul(w, w1);
    }
}

// ---------------------------------------------------------------------------
// Kernel 1: packed complex FFT (2 real channels per FFT), radix-16 Stockham,
// 4 channel-pairs per block (serial, fixed order), amplitudes accumulated in
// smem. grid = B*8 blocks, 256 threads. ~40KB static smem.
// ---------------------------------------------------------------------------
__global__ __launch_bounds__(256) void fft_kernel()
{
    __shared__ float2 z[T_LEN];     // 32 KB, SWZ-indexed
    __shared__ float  amp[NFREQ];   // 8.2 KB amplitude accumulator

    const int tid = threadIdx.x;
    const int blk = blockIdx.x;     // b * 8 + group

    for (int k = tid; k < NFREQ; k += 256) amp[k] = 0.0f;

    for (int pp = 0; pp < 4; pp++) {
        const float2* xcb = g_xc + (size_t)(blk * 4 + pp) * T_LEN;
        float2 v[16];

        // ---- Step 1 (Ns = 1): coalesced load, DFT16, store ----
        #pragma unroll
        for (int r = 0; r < 16; r++)
            v[r] = xcb[tid + 256 * r];
        dft16(v);
        {
            const int base = tid * 16;       // expand(j,1,16)
            #pragma unroll
            for (int r = 0; r < 16; r++)
                z[SWZ(base + r)] = v[PREG(r)];
        }
        __syncthreads();

        // ---- Step 2 (Ns = 16) ----
        #pragma unroll
        for (int r = 0; r < 16; r++)
            v[r] = z[SWZ(tid + 256 * r)];
        step_twiddle(v, tid & 15, 1.0f / 256.0f);
        dft16(v);
        __syncthreads();
        {
            const int base = (tid >> 4) * 256 + (tid & 15);   // expand(j,16,16)
            #pragma unroll
            for (int r = 0; r < 16; r++)
                z[SWZ(base + 16 * r)] = v[PREG(r)];
        }
        __syncthreads();

        // ---- Step 3 (Ns = 256) ----
        #pragma unroll
        for (int r = 0; r < 16; r++)
            v[r] = z[SWZ(tid + 256 * r)];
        step_twiddle(v, tid, 1.0f / 4096.0f);
        dft16(v);
        __syncthreads();
        {
            const int base = tid;            // expand(j,256,16) = j for j<256
            #pragma unroll
            for (int r = 0; r < 16; r++)
                z[SWZ(base + 256 * r)] = v[PREG(r)];
        }
        __syncthreads();

        // ---- Unpack Hermitian halves, accumulate |X1[k]| + |X2[k]| ----
        for (int k = tid; k < NFREQ; k += 256) {
            const float2 a  = z[SWZ(k)];
            const float2 bm = z[SWZ((T_LEN - k) & (T_LEN - 1))];
            const float sr = 0.5f * (a.x + bm.x);
            const float si = 0.5f * (a.y - bm.y);
            const float dr = 0.5f * (a.x - bm.x);
            const float di = 0.5f * (a.y + bm.y);
            amp[k] += sqrtf(sr * sr + si * si) + sqrtf(di * di + dr * dr);
        }
        __syncthreads();   // amp/z reuse safe before next pair
    }

    float* out = g_part + (size_t)blk * FPAD;
    for (int k = tid; k < NFREQ; k += 256)
        out[k] = amp[k];
}

// ---------------------------------------------------------------------------
// Kernel 2a: reduce NGRP group partials per (batch, freq-chunk).
// grid = (9, B), 256 threads; one thread per frequency.
// ---------------------------------------------------------------------------
__global__ __launch_bounds__(256) void reduce_kernel()
{
    const int b = blockIdx.y;
    const int k = blockIdx.x * 256 + threadIdx.x;
    if (k >= NFREQ) return;
    float s = 0.0f;
    #pragma unroll
    for (int g = 0; g < NGRP; g++)
        s += g_part[(size_t)(b * NGRP + g) * FPAD + k];
    g_amps[b * FPAD + k] = s;
}

// ---------------------------------------------------------------------------
// Kernel 2b: top-6 per batch from g_amps (value desc, smaller idx on tie).
// grid = B, 1024 threads; amplitudes cached in smem.
// ---------------------------------------------------------------------------
__global__ __launch_bounds__(1024) void topk_kernel()
{
    __shared__ float a[NFREQ];
    __shared__ float sv[32];
    __shared__ int   si[32];

    const int b    = blockIdx.x;
    const int tid  = threadIdx.x;
    const int lane = tid & 31;
    const int warp = tid >> 5;

    for (int k = tid; k < NFREQ; k += 1024)
        a[k] = g_amps[b * FPAD + k];
    __syncthreads();

    for (int sel = 0; sel < NCAND; sel++) {
        float bv = -1e30f;
        int   bi = 0x7fffffff;
        for (int k = tid; k < NFREQ; k += 1024) {
            const float v = a[k];
            if (v > bv) { bv = v; bi = k; }   // ascending scan -> smallest idx on tie
        }
        #pragma unroll
        for (int o = 16; o > 0; o >>= 1) {
            const float v2 = __shfl_xor_sync(0xffffffffu, bv, o);
            const int   i2 = __shfl_xor_sync(0xffffffffu, bi, o);
            argmax2(bv, bi, v2, i2);
        }
        if (lane == 0) { sv[warp] = bv; si[warp] = bi; }
        __syncthreads();
        if (warp == 0) {
            float v = sv[lane];
            int   i = si[lane];
            #pragma unroll
            for (int o = 16; o > 0; o >>= 1) {
                const float v2 = __shfl_xor_sync(0xffffffffu, v, o);
                const int   i2 = __shfl_xor_sync(0xffffffffu, i, o);
                argmax2(v, i, v2, i2);
            }
            if (lane == 0) {
                g_topidx[b * NCAND + sel] = i;
                a[i] = -1e30f;
            }
        }
        __syncthreads();
    }
}

// ---------------------------------------------------------------------------
// Kernel 3: fill r[b][j][t] for unique candidate periods only (duplicates
// dedup'd first-occurrence-wins; score recomputes the same map).
// grid = (16 t-chunks, B). 256 threads, no smem -> high occupancy.
// ---------------------------------------------------------------------------
__global__ __launch_bounds__(256) void fill_kernel(const float* __restrict__ x)
{
    const int b   = blockIdx.y;
    const int t0  = blockIdx.x * 256;
    const int tid = threadIdx.x;

    int p[NCAND];
    bool uniq[NCAND];
    #pragma unroll
    for (int j = 0; j < NCAND; j++)
        p[j] = cand_period(g_topidx[b * NCAND + j]);
    #pragma unroll
    for (int j = 0; j < NCAND; j++) {
        bool u = true;
        #pragma unroll
        for (int k = 0; k < NCAND; k++)
            if (k < j && p[k] == p[j]) u = false;
        uniq[j] = u;
    }

    const float* xb = x + (size_t)b * T_LEN * C_CH;
    const int lane = tid & 31;
    const int warp = tid >> 5;
    const int sub  = lane >> 4;          // which of the warp's 2 rows
    const int ch   = (lane & 15) << 2;   // float offset within the row
    const bool wl  = (lane & 15) == 0;   // writer lane for this half-warp

    for (int i = 0; i < 16; i++) {
        const int t = t0 + i * 16 + warp * 2 + sub;
        const float4 a = *(const float4*)(xb + (size_t)t * C_CH + ch);

        #pragma unroll
        for (int j = 0; j < NCAND; j++) {
            if (!uniq[j]) continue;
            const int t2 = t + p[j];
            float r = 0.0f;
            if (t2 < T_LEN) {
                const float4 bv = *(const float4*)(xb + (size_t)t2 * C_CH + ch);
                r = a.x * bv.x + a.y * bv.y + a.z * bv.z + a.w * bv.w;
            }
            #pragma unroll
            for (int o = 8; o > 0; o >>= 1)
                r += __shfl_down_sync(0xffffffffu, r, o, 16);
            if (wl) g_r[(size_t)(b * NCAND + j) * T_LEN + t] = r;
        }
    }
}

// ---------------------------------------------------------------------------
// Kernel 4: score per (batch, candidate) via PREFIX SUMS.
// grid = (NCAND, B). 256 threads. Reads r of the FIRST candidate with the
// same period (matches fill's dedup). All reductions fixed-order.
// ---------------------------------------------------------------------------
__global__ __launch_bounds__(256) void score_kernel()
{
    __shared__ float CR[T_LEN + 1];
    __shared__ float CQ[T_LEN + 1];
    __shared__ float wtot[8];
    __shared__ float woff_r[8];
    __shared__ float woff_q[8];
    __shared__ float red[256];

    const int j    = blockIdx.x;
    const int b    = blockIdx.y;
    const int tid  = threadIdx.x;
    const int lane = tid & 31;
    const int warp = tid >> 5;

    // period + dedup source index (first j' with equal period)
    int p = 0, jsrc = j;
    {
        int pj[NCAND];
        #pragma unroll
        for (int k = 0; k < NCAND; k++)
            pj[k] = cand_period(g_topidx[b * NCAND + k]);
        p = pj[j];
        #pragma unroll
        for (int k = NCAND - 1; k >= 0; k--)
            if (k <= j && pj[k] == p) jsrc = k;
    }

    const float* rs = g_r + (size_t)(b * NCAND + jsrc) * T_LEN;
    const float* qs = g_q + (size_t)b * T_LEN;

    // ---- Load 16 contiguous elements each, local inclusive scan ----
    const int base = tid * 16;
    float lr[16], lq[16];
    {
        float sr = 0.0f, sq = 0.0f;
        #pragma unroll
        for (int k = 0; k < 16; k++) {
            sr += rs[base + k]; lr[k] = sr;
            sq += qs[base + k]; lq[k] = sq;
        }
    }
    const float totr = lr[15], totq = lq[15];

    // ---- Scan the 256 per-thread totals (warp shuffle scan + warp offsets) ----
    float ir = totr, iq = totq;          // inclusive within warp
    #pragma unroll
    for (int o = 1; o < 32; o <<= 1) {
        const float vr = __shfl_up_sync(0xffffffffu, ir, o);
        const float vq = __shfl_up_sync(0xffffffffu, iq, o);
        if (lane >= o) { ir += vr; iq += vq; }
    }
    if (lane == 31) { wtot[warp] = ir; woff_q[warp] = iq; }  // warp totals (q via woff_q temp)
    __syncthreads();
    if (warp == 0 && lane == 0) {
        float ar = 0.0f, aq = 0.0f;
        #pragma unroll
        for (int w = 0; w < 8; w++) {
            const float tr = wtot[w], tq = woff_q[w];
            woff_r[w] = ar; woff_q[w] = aq;   // exclusive warp offsets
            ar += tr; aq += tq;
        }
    }
    __syncthreads();
    const float offr = woff_r[warp] + ir - totr;   // exclusive prefix for this thread
    const float offq = woff_q[warp] + iq - totq;

    // ---- Write inclusive scans to smem (CR[k] = sum of first k elements) ----
    if (tid == 0) { CR[0] = 0.0f; CQ[0] = 0.0f; }
    #pragma unroll
    for (int k = 0; k < 16; k++) {
        CR[base + k + 1] = offr + lr[k];
        CQ[base + k + 1] = offq + lq[k];
    }
    __syncthreads();

    // ---- Segment cosines, O(1) each ----
    const int nper = T_LEN / p;
    const int nseg = nper - 1;           // >= 1 since p <= T/2
    float wsum = 0.0f;
    for (int i = tid; i < nseg; i += 256) {
        const int s  = i * p;
        const int e  = s + p;
        const int e2 = e + p;            // <= nper*p <= T
        const float dots = CR[e] - CR[s];
        const float na = sqrtf(fmaxf(CQ[e]  - CQ[s], 0.0f));
        const float nb = sqrtf(fmaxf(CQ[e2] - CQ[e], 0.0f));
        wsum += dots / fmaxf(na * nb, 1e-8f);
    }

    // ---- Fixed-order block reduction ----
    red[tid] = wsum;
    __syncthreads();
    for (int s = 128; s > 0; s >>= 1) {
        if (tid < s) red[tid] += red[tid + s];
        __syncthreads();
    }
    if (tid == 0)
        g_scores[b * NCAND + j] = red[0] / (float)nseg;
}

// ---------------------------------------------------------------------------
// Kernel 5: final selection -> out = periods[64*3] ++ weights[64*3]
// ---------------------------------------------------------------------------
__global__ void select_kernel(float* __restrict__ out)
{
    const int b = blockIdx.x * blockDim.x + threadIdx.x;
    if (b >= B_SZ) return;

    int   pe[TOPK];
    float wt[TOPK];
    int cnt = 0;
    for (int j = 0; j < NCAND; j++) {
        const int idx = g_topidx[b * NCAND + j];
        const float pf  = 4096.0f / (float)(idx + 1);
        const float pfl = floorf(pf);
        const bool in_range     = (pf  >= 2.0f) && (pf  <= 2048.0f);
        const bool in_range_int = (pfl >= 2.0f) && (pfl <= 2048.0f);
        int pi = (int)pfl;
        pi = min(max(pi, 2), T_LEN / 2);
        const bool valid = in_range && in_range_int && (g_scores[b * NCAND + j] > 0.2f);
        if (valid && cnt < TOPK) { pe[cnt] = pi; wt[cnt] = 1.0f; cnt++; }
    }
    const int addp[3] = {1024, 1365, 2048};   // T//4, T//3, T//2 (int(T/1.5)=2730 > half)
    for (int j = cnt; j < TOPK; j++) {
        pe[j] = addp[min(j - cnt, 2)];
        wt[j] = 0.5f;
    }
    #pragma unroll
    for (int j = 0; j < TOPK; j++) {
        out[b * TOPK + j]                = (float)pe[j];
        out[B_SZ * TOPK + b * TOPK + j]  = wt[j];
    }
}

// ---------------------------------------------------------------------------
extern "C" void kernel_launch(void* const* d_in, const int* in_sizes, int n_in,
                              void* d_out, int out_size)
{
    const float* x  = (const float*)d_in[0];
    float* out = (float*)d_out;

    transpose_kernel<<<dim3(T_LEN / 64, B_SZ), 256>>>(x);
    fft_kernel<<<B_SZ * NGRP, 256>>>();
    reduce_kernel<<<dim3(9, B_SZ), 256>>>();
    topk_kernel<<<B_SZ, 1024>>>();
    fill_kernel<<<dim3(16, B_SZ), 256>>>(x);
    score_kernel<<<dim3(NCAND, B_SZ), 256>>>();
    select_kernel<<<1, 64>>>(out);
}

// round 13
// speedup vs baseline: 1.1156x; 1.1156x over previous
#include <cuda_runtime.h>
#include <cuda_bf16.h>
#include <math.h>

// Problem constants
#define T_LEN  4096
#define C_CH   64
#define B_SZ   64
#define NFREQ  2049            // T/2 + 1
#define FPAD   2052            // padded row for alignment
#define NCAND  6               // 2 * TOP_K
#define TOPK   3

// Bank-conflict-killing smem swizzle for float2 z[4096]
#define SWZ(i) ((i) ^ (((i) >> 4) & 15))

// ---------------------------------------------------------------------------
// Scratch (device globals; no allocations allowed)
// ---------------------------------------------------------------------------
__device__ float2 g_xc [B_SZ * 32 * T_LEN];  // packed transpose: (x[t,2p], x[t,2p+1])
__device__ float  g_part[B_SZ * 32 * FPAD];  // per-(batch, channel-pair) amplitude sums
__device__ int    g_topidx[B_SZ * NCAND];    // top-6 frequency indices per batch
__device__ float  g_scores[B_SZ * NCAND];    // autocorr scores per candidate
__device__ float  g_q [B_SZ * T_LEN];        // ||x[b,t]||^2
__device__ float  g_r [B_SZ * NCAND * T_LEN];// <x[b,t], x[b,t+p_j]>

__device__ __forceinline__ float2 cmul(float2 a, float2 b) {
    return make_float2(a.x * b.x - a.y * b.y, a.x * b.y + a.y * b.x);
}

__device__ __forceinline__ int cand_period(int idx) {
    const float pf = 4096.0f / (float)(idx + 1);
    int p = (int)floorf(pf);
    return min(max(p, 2), T_LEN / 2);
}

// argmax combine: higher value wins; tie -> smaller index
__device__ __forceinline__ void argmax2(float& v, int& i, float v2, int i2) {
    if (v2 > v || (v2 == v && i2 < i)) { v = v2; i = i2; }
}

// ---------------------------------------------------------------------------
// Kernel 0: transpose/pack x[b,t,c] -> xc[b, c/2, t] as float2 AND compute
// q[b][t] = ||x[b,t]||^2 on the fly. grid = (T/64, B), 256 threads.
// ---------------------------------------------------------------------------
__global__ __launch_bounds__(256) void transpose_kernel(const float* __restrict__ x)
{
    __shared__ float tile[64][68];       // 64 t-rows x 64 channels, pad 68 (f4-aligned)

    const int b   = blockIdx.y;
    const int t0  = blockIdx.x * 64;
    const int tid = threadIdx.x;

    // Load: thread handles row r = tid/4, 16 floats starting at (tid%4)*16.
    {
        const int r  = tid >> 2;
        const int c0 = (tid & 3) * 16;
        const float* src = x + (size_t)b * T_LEN * C_CH + (size_t)(t0 + r) * C_CH + c0;
        float qp = 0.0f;
        #pragma unroll
        for (int i = 0; i < 4; i++) {
            const float4 v = *(const float4*)(src + 4 * i);
            *(float4*)&tile[r][c0 + 4 * i] = v;
            qp += v.x * v.x + v.y * v.y + v.z * v.z + v.w * v.w;
        }
        // reduce across the 4 threads covering this row (lanes 4k..4k+3)
        qp += __shfl_down_sync(0xffffffffu, qp, 2, 4);
        qp += __shfl_down_sync(0xffffffffu, qp, 1, 4);
        if ((tid & 3) == 0)
            g_q[b * T_LEN + t0 + r] = qp;
    }
    __syncthreads();

    // Store: warp w covers pairs 4w..4w+3; 8-lane group per pair, consecutive t.
    {
        const int lane = tid & 31;
        const int warp = tid >> 5;
        const int p    = warp * 4 + (lane >> 3);   // 0..31
        const int tloc = lane & 7;
        float2* dst = g_xc + ((size_t)b * 32 + p) * T_LEN + t0;
        #pragma unroll
        for (int i = 0; i < 8; i++) {
            const int t = tloc + 8 * i;
            dst[t] = *(const float2*)&tile[t][2 * p];
        }
    }
}

// DFT-4 in place: (a,b,c,d) -> (X0,X1,X2,X3), W4 = exp(-2*pi*i/4) = -i
__device__ __forceinline__ void dft4(float2& a, float2& b, float2& c, float2& d)
{
    const float2 s02 = make_float2(a.x + c.x, a.y + c.y);
    const float2 d02 = make_float2(a.x - c.x, a.y - c.y);
    const float2 s13 = make_float2(b.x + d.x, b.y + d.y);
    const float2 d13 = make_float2(b.x - d.x, b.y - d.y);
    a = make_float2(s02.x + s13.x, s02.y + s13.y);
    b = make_float2(d02.x + d13.y, d02.y - d13.x);   // d02 - i*d13
    c = make_float2(s02.x - s13.x, s02.y - s13.y);
    d = make_float2(d02.x - d13.y, d02.y + d13.x);   // d02 + i*d13
}

// In-place DFT-16. Input natural order v[0..15]; output X[k1+4k2] lives in
// v[4k1+k2] (use PREG to fetch X[r]).
#define PREG(r) (4 * ((r) & 3) + ((r) >> 2))
__device__ __forceinline__ void dft16(float2 v[16])
{
    const float C1 = 0.92387953251128674f;   // cos(pi/8)
    const float S1 = 0.38268343236508978f;   // sin(pi/8)
    const float C2 = 0.70710678118654752f;   // cos(pi/4)

    #pragma unroll
    for (int t2 = 0; t2 < 4; t2++)
        dft4(v[t2], v[4 + t2], v[8 + t2], v[12 + t2]);

    v[5]  = cmul(v[5],  make_float2( C1, -S1));  // W^1
    v[6]  = cmul(v[6],  make_float2( C2, -C2));  // W^2
    v[7]  = cmul(v[7],  make_float2( S1, -C1));  // W^3
    v[9]  = cmul(v[9],  make_float2( C2, -C2));  // W^2
    v[10] = make_float2(v[10].y, -v[10].x);      // W^4 = -i
    v[11] = cmul(v[11], make_float2(-C2, -C2));  // W^6
    v[13] = cmul(v[13], make_float2( S1, -C1));  // W^3
    v[14] = cmul(v[14], make_float2(-C2, -C2));  // W^6
    v[15] = cmul(v[15], make_float2(-C1,  S1));  // W^9

    #pragma unroll
    for (int k1 = 0; k1 < 4; k1++)
        dft4(v[4 * k1], v[4 * k1 + 1], v[4 * k1 + 2], v[4 * k1 + 3]);
}

// Apply step twiddles v[r] *= w1^r using a log-depth power tree.
__device__ __forceinline__ void step_twiddle(float2 v[16], int m, float invNs16)
{
    const float ang = -6.283185307179586f * (float)m * invNs16;
    float s, c;
    sincosf(ang, &s, &c);
    const float2 w1 = make_float2(c, s);
    const float2 w2 = cmul(w1, w1);
    const float2 w4 = cmul(w2, w2);
    const float2 w8 = cmul(w4, w4);
    const float2 w3  = cmul(w2, w1);
    const float2 w5  = cmul(w4, w1);
    const float2 w6  = cmul(w4, w2);
    const float2 w7  = cmul(w4, w3);
    const float2 w9  = cmul(w8, w1);
    const float2 w10 = cmul(w8, w2);
    const float2 w11 = cmul(w8, w3);
    const float2 w12 = cmul(w8, w4);
    const float2 w13 = cmul(w8, w5);
    const float2 w14 = cmul(w8, w6);
    const float2 w15 = cmul(w8, w7);
    v[1]  = cmul(v[1],  w1);
    v[2]  = cmul(v[2],  w2);
    v[3]  = cmul(v[3],  w3);
    v[4]  = cmul(v[4],  w4);
    v[5]  = cmul(v[5],  w5);
    v[6]  = cmul(v[6],  w6);
    v[7]  = cmul(v[7],  w7);
    v[8]  = cmul(v[8],  w8);
    v[9]  = cmul(v[9],  w9);
    v[10] = cmul(v[10], w10);
    v[11] = cmul(v[11], w11);
    v[12] = cmul(v[12], w12);
    v[13] = cmul(v[13], w13);
    v[14] = cmul(v[14], w14);
    v[15] = cmul(v[15], w15);
}

// ---------------------------------------------------------------------------
// Kernel 1: packed complex FFT (2 real channels per FFT), radix-16 Stockham,
// natural-order output, + Hermitian unpack. Loads from g_xc (coalesced).
// grid = B*32 blocks, 256 threads. 32KB static smem.
// ---------------------------------------------------------------------------
__global__ __launch_bounds__(256) void fft_kernel()
{
    __shared__ float2 z[T_LEN];     // 32 KB, SWZ-indexed

    const int tid  = threadIdx.x;
    const float2* xcb = g_xc + (size_t)blockIdx.x * T_LEN;

    float2 v[16];

    // ---- Step 1 (Ns = 1): coalesced load, DFT16, store ----
    #pragma unroll
    for (int r = 0; r < 16; r++)
        v[r] = xcb[tid + 256 * r];
    dft16(v);
    {
        const int base = tid * 16;       // expand(j,1,16)
        #pragma unroll
        for (int r = 0; r < 16; r++)
            z[SWZ(base + r)] = v[PREG(r)];
    }
    __syncthreads();

    // ---- Step 2 (Ns = 16) ----
    #pragma unroll
    for (int r = 0; r < 16; r++)
        v[r] = z[SWZ(tid + 256 * r)];
    step_twiddle(v, tid & 15, 1.0f / 256.0f);
    dft16(v);
    __syncthreads();
    {
        const int base = (tid >> 4) * 256 + (tid & 15);   // expand(j,16,16)
        #pragma unroll
        for (int r = 0; r < 16; r++)
            z[SWZ(base + 16 * r)] = v[PREG(r)];
    }
    __syncthreads();

    // ---- Step 3 (Ns = 256) ----
    #pragma unroll
    for (int r = 0; r < 16; r++)
        v[r] = z[SWZ(tid + 256 * r)];
    step_twiddle(v, tid, 1.0f / 4096.0f);
    dft16(v);
    __syncthreads();
    {
        const int base = tid;            // expand(j,256,16) = j for j<256
        #pragma unroll
        for (int r = 0; r < 16; r++)
            z[SWZ(base + 256 * r)] = v[PREG(r)];
    }
    __syncthreads();

    // ---- Unpack Hermitian halves -> |X1[k]| + |X2[k]| for k in [0, 2048] ----
    float* out = g_part + (size_t)blockIdx.x * FPAD;
    for (int k = tid; k < NFREQ; k += 256) {
        const float2 a  = z[SWZ(k)];
        const float2 bm = z[SWZ((T_LEN - k) & (T_LEN - 1))];
        const float sr = 0.5f * (a.x + bm.x);
        const float si = 0.5f * (a.y - bm.y);
        const float dr = 0.5f * (a.x - bm.x);
        const float di = 0.5f * (a.y + bm.y);
        out[k] = sqrtf(sr * sr + si * si) + sqrtf(di * di + dr * dr);
    }
}

// ---------------------------------------------------------------------------
// Kernel 2: fused reduce + top-6 per batch. 1024 threads sum the 32
// channel-pair partials (fixed order, coalesced, 32-way MLP) into smem,
// then 6 shuffle-argmax rounds (value desc, smaller idx on tie). grid = B.
// ---------------------------------------------------------------------------
__global__ __launch_bounds__(1024) void redtopk_kernel()
{
    __shared__ float a[NFREQ];
    __shared__ float sv[32];
    __shared__ int   si[32];

    const int b    = blockIdx.x;
    const int tid  = threadIdx.x;
    const int lane = tid & 31;
    const int warp = tid >> 5;

    for (int k = tid; k < NFREQ; k += 1024) {
        float s = 0.0f;
        #pragma unroll 8
        for (int p = 0; p < 32; p++)
            s += g_part[(size_t)(b * 32 + p) * FPAD + k];
        a[k] = s;
    }
    __syncthreads();

    for (int sel = 0; sel < NCAND; sel++) {
        float bv = -1e30f;
        int   bi = 0x7fffffff;
        for (int k = tid; k < NFREQ; k += 1024) {
            const float v = a[k];
            if (v > bv) { bv = v; bi = k; }   // ascending scan -> smallest idx on tie
        }
        #pragma unroll
        for (int o = 16; o > 0; o >>= 1) {
            const float v2 = __shfl_xor_sync(0xffffffffu, bv, o);
            const int   i2 = __shfl_xor_sync(0xffffffffu, bi, o);
            argmax2(bv, bi, v2, i2);
        }
        if (lane == 0) { sv[warp] = bv; si[warp] = bi; }
        __syncthreads();
        if (warp == 0) {
            float v = sv[lane];
            int   i = si[lane];
            #pragma unroll
            for (int o = 16; o > 0; o >>= 1) {
                const float v2 = __shfl_xor_sync(0xffffffffu, v, o);
                const int   i2 = __shfl_xor_sync(0xffffffffu, i, o);
                argmax2(v, i, v2, i2);
            }
            if (lane == 0) {
                g_topidx[b * NCAND + sel] = i;
                a[i] = -1e30f;
            }
        }
        __syncthreads();
    }
}

// ---------------------------------------------------------------------------
// Kernel 3: fill r[b][j][t] for unique candidate periods only (duplicates
// dedup'd first-occurrence-wins; score recomputes the same map).
// grid = (16 t-chunks, B). 256 threads, no smem -> high occupancy.
// ---------------------------------------------------------------------------
__global__ __launch_bounds__(256) void fill_kernel(const float* __restrict__ x)
{
    const int b   = blockIdx.y;
    const int t0  = blockIdx.x * 256;
    const int tid = threadIdx.x;

    int p[NCAND];
    bool uniq[NCAND];
    #pragma unroll
    for (int j = 0; j < NCAND; j++)
        p[j] = cand_period(g_topidx[b * NCAND + j]);
    #pragma unroll
    for (int j = 0; j < NCAND; j++) {
        bool u = true;
        #pragma unroll
        for (int k = 0; k < NCAND; k++)
            if (k < j && p[k] == p[j]) u = false;
        uniq[j] = u;
    }

    const float* xb = x + (size_t)b * T_LEN * C_CH;
    const int lane = tid & 31;
    const int warp = tid >> 5;
    const int sub  = lane >> 4;          // which of the warp's 2 rows
    const int ch   = (lane & 15) << 2;   // float offset within the row
    const bool wl  = (lane & 15) == 0;   // writer lane for this half-warp

    for (int i = 0; i < 16; i++) {
        const int t = t0 + i * 16 + warp * 2 + sub;
        const float4 a = *(const float4*)(xb + (size_t)t * C_CH + ch);

        #pragma unroll
        for (int j = 0; j < NCAND; j++) {
            if (!uniq[j]) continue;
            const int t2 = t + p[j];
            float r = 0.0f;
            if (t2 < T_LEN) {
                const float4 bv = *(const float4*)(xb + (size_t)t2 * C_CH + ch);
                r = a.x * bv.x + a.y * bv.y + a.z * bv.z + a.w * bv.w;
            }
            #pragma unroll
            for (int o = 8; o > 0; o >>= 1)
                r += __shfl_down_sync(0xffffffffu, r, o, 16);
            if (wl) g_r[(size_t)(b * NCAND + j) * T_LEN + t] = r;
        }
    }
}

// ---------------------------------------------------------------------------
// Kernel 4: score per (batch, candidate) via PREFIX SUMS.
// grid = (NCAND, B). 256 threads. Reads r of the FIRST candidate with the
// same period (matches fill's dedup). All reductions fixed-order.
// ---------------------------------------------------------------------------
__global__ __launch_bounds__(256) void score_kernel()
{
    __shared__ float CR[T_LEN + 1];
    __shared__ float CQ[T_LEN + 1];
    __shared__ float wtot[8];
    __shared__ float woff_r[8];
    __shared__ float woff_q[8];
    __shared__ float red[256];

    const int j    = blockIdx.x;
    const int b    = blockIdx.y;
    const int tid  = threadIdx.x;
    const int lane = tid & 31;
    const int warp = tid >> 5;

    // period + dedup source index (first j' with equal period)
    int p = 0, jsrc = j;
    {
        int pj[NCAND];
        #pragma unroll
        for (int k = 0; k < NCAND; k++)
            pj[k] = cand_period(g_topidx[b * NCAND + k]);
        p = pj[j];
        #pragma unroll
        for (int k = NCAND - 1; k >= 0; k--)
            if (k <= j && pj[k] == p) jsrc = k;
    }

    const float* rs = g_r + (size_t)(b * NCAND + jsrc) * T_LEN;
    const float* qs = g_q + (size_t)b * T_LEN;

    // ---- Load 16 contiguous elements each, local inclusive scan ----
    const int base = tid * 16;
    float lr[16], lq[16];
    {
        float sr = 0.0f, sq = 0.0f;
        #pragma unroll
        for (int k = 0; k < 16; k++) {
            sr += rs[base + k]; lr[k] = sr;
            sq += qs[base + k]; lq[k] = sq;
        }
    }
    const float totr = lr[15], totq = lq[15];

    // ---- Scan the 256 per-thread totals (warp shuffle scan + warp offsets) ----
    float ir = totr, iq = totq;          // inclusive within warp
    #pragma unroll
    for (int o = 1; o < 32; o <<= 1) {
        const float vr = __shfl_up_sync(0xffffffffu, ir, o);
        const float vq = __shfl_up_sync(0xffffffffu, iq, o);
        if (lane >= o) { ir += vr; iq += vq; }
    }
    if (lane == 31) { wtot[warp] = ir; woff_q[warp] = iq; }  // warp totals (q via woff_q temp)
    __syncthreads();
    if (warp == 0 && lane == 0) {
        float ar = 0.0f, aq = 0.0f;
        #pragma unroll
        for (int w = 0; w < 8; w++) {
            const float tr = wtot[w], tq = woff_q[w];
            woff_r[w] = ar; woff_q[w] = aq;   // exclusive warp offsets
            ar += tr; aq += tq;
        }
    }
    __syncthreads();
    const float offr = woff_r[warp] + ir - totr;   // exclusive prefix for this thread
    const float offq = woff_q[warp] + iq - totq;

    // ---- Write inclusive scans to smem (CR[k] = sum of first k elements) ----
    if (tid == 0) { CR[0] = 0.0f; CQ[0] = 0.0f; }
    #pragma unroll
    for (int k = 0; k < 16; k++) {
        CR[base + k + 1] = offr + lr[k];
        CQ[base + k + 1] = offq + lq[k];
    }
    __syncthreads();

    // ---- Segment cosines, O(1) each ----
    const int nper = T_LEN / p;
    const int nseg = nper - 1;           // >= 1 since p <= T/2
    float wsum = 0.0f;
    for (int i = tid; i < nseg; i += 256) {
        const int s  = i * p;
        const int e  = s + p;
        const int e2 = e + p;            // <= nper*p <= T
        const float dots = CR[e] - CR[s];
        const float na = sqrtf(fmaxf(CQ[e]  - CQ[s], 0.0f));
        const float nb = sqrtf(fmaxf(CQ[e2] - CQ[e], 0.0f));
        wsum += dots / fmaxf(na * nb, 1e-8f);
    }

    // ---- Fixed-order block reduction ----
    red[tid] = wsum;
    __syncthreads();
    for (int s = 128; s > 0; s >>= 1) {
        if (tid < s) red[tid] += red[tid + s];
        __syncthreads();
    }
    if (tid == 0)
        g_scores[b * NCAND + j] = red[0] / (float)nseg;
}

// ---------------------------------------------------------------------------
// Kernel 5: final selection -> out = periods[64*3] ++ weights[64*3]
// ---------------------------------------------------------------------------
__global__ void select_kernel(float* __restrict__ out)
{
    const int b = blockIdx.x * blockDim.x + threadIdx.x;
    if (b >= B_SZ) return;

    int   pe[TOPK];
    float wt[TOPK];
    int cnt = 0;
    for (int j = 0; j < NCAND; j++) {
        const int idx = g_topidx[b * NCAND + j];
        const float pf  = 4096.0f / (float)(idx + 1);
        const float pfl = floorf(pf);
        const bool in_range     = (pf  >= 2.0f) && (pf  <= 2048.0f);
        const bool in_range_int = (pfl >= 2.0f) && (pfl <= 2048.0f);
        int pi = (int)pfl;
        pi = min(max(pi, 2), T_LEN / 2);
        const bool valid = in_range && in_range_int && (g_scores[b * NCAND + j] > 0.2f);
        if (valid && cnt < TOPK) { pe[cnt] = pi; wt[cnt] = 1.0f; cnt++; }
    }
    const int addp[3] = {1024, 1365, 2048};   // T//4, T//3, T//2 (int(T/1.5)=2730 > half)
    for (int j = cnt; j < TOPK; j++) {
        pe[j] = addp[min(j - cnt, 2)];
        wt[j] = 0.5f;
    }
    #pragma unroll
    for (int j = 0; j < TOPK; j++) {
        out[b * TOPK + j]                = (float)pe[j];
        out[B_SZ * TOPK + b * TOPK + j]  = wt[j];
    }
}

// ---------------------------------------------------------------------------
extern "C" void kernel_launch(void* const* d_in, const int* in_sizes, int n_in,
                              void* d_out, int out_size)
{
    const float* x  = (const float*)d_in[0];
    float* out = (float*)d_out;

    transpose_kernel<<<dim3(T_LEN / 64, B_SZ), 256>>>(x);
    fft_kernel<<<B_SZ * 32, 256>>>();
    redtopk_kernel<<<B_SZ, 1024>>>();
    fill_kernel<<<dim3(16, B_SZ), 256>>>(x);
    score_kernel<<<dim3(NCAND, B_SZ), 256>>>();
    select_kernel<<<1, 64>>>(out);
}

// round 17
// speedup vs baseline: 1.2238x; 1.0970x over previous
#include <cuda_runtime.h>
#include <cuda_bf16.h>
#include <math.h>

// Problem constants
#define T_LEN  4096
#define C_CH   64
#define B_SZ   64
#define NFREQ  2049            // T/2 + 1
#define FPAD   2052            // padded row for alignment
#define NCAND  6               // 2 * TOP_K
#define TOPK   3

// Bank-conflict-killing smem swizzle for float2 z[4096]
#define SWZ(i) ((i) ^ (((i) >> 4) & 15))

// ---------------------------------------------------------------------------
// Scratch (device globals; no allocations allowed)
// ---------------------------------------------------------------------------
__device__ float2 g_xc [B_SZ * 32 * T_LEN];  // packed transpose: (x[t,2p], x[t,2p+1])
__device__ float  g_part[B_SZ * 32 * FPAD];  // per-(batch, channel-pair) amplitude sums
__device__ int    g_topidx[B_SZ * NCAND];    // top-6 frequency indices per batch
__device__ float  g_scores[B_SZ * NCAND];    // autocorr scores per candidate
__device__ float  g_q [B_SZ * T_LEN];        // ||x[b,t]||^2
__device__ float  g_r [B_SZ * NCAND * T_LEN];// <x[b,t], x[b,t+p_j]>

__device__ __forceinline__ float2 cmul(float2 a, float2 b) {
    return make_float2(a.x * b.x - a.y * b.y, a.x * b.y + a.y * b.x);
}

__device__ __forceinline__ int cand_period(int idx) {
    const float pf = 4096.0f / (float)(idx + 1);
    int p = (int)floorf(pf);
    return min(max(p, 2), T_LEN / 2);
}

// argmax combine: higher value wins; tie -> smaller index
__device__ __forceinline__ void argmax2(float& v, int& i, float v2, int i2) {
    if (v2 > v || (v2 == v && i2 < i)) { v = v2; i = i2; }
}

// ---------------------------------------------------------------------------
// Kernel 0: transpose/pack x[b,t,c] -> xc[b, c/2, t] as float2 AND compute
// q[b][t] = ||x[b,t]||^2 on the fly. grid = (T/64, B), 256 threads.
// ---------------------------------------------------------------------------
__global__ __launch_bounds__(256) void transpose_kernel(const float* __restrict__ x)
{
    __shared__ float tile[64][68];       // 64 t-rows x 64 channels, pad 68 (f4-aligned)

    const int b   = blockIdx.y;
    const int t0  = blockIdx.x * 64;
    const int tid = threadIdx.x;

    // Load: thread handles row r = tid/4, 16 floats starting at (tid%4)*16.
    {
        const int r  = tid >> 2;
        const int c0 = (tid & 3) * 16;
        const float* src = x + (size_t)b * T_LEN * C_CH + (size_t)(t0 + r) * C_CH + c0;
        float qp = 0.0f;
        #pragma unroll
        for (int i = 0; i < 4; i++) {
            const float4 v = *(const float4*)(src + 4 * i);
            *(float4*)&tile[r][c0 + 4 * i] = v;
            qp += v.x * v.x + v.y * v.y + v.z * v.z + v.w * v.w;
        }
        // reduce across the 4 threads covering this row (lanes 4k..4k+3)
        qp += __shfl_down_sync(0xffffffffu, qp, 2, 4);
        qp += __shfl_down_sync(0xffffffffu, qp, 1, 4);
        if ((tid & 3) == 0)
            g_q[b * T_LEN + t0 + r] = qp;
    }
    __syncthreads();

    // Store: warp w covers pairs 4w..4w+3; 8-lane group per pair, consecutive t.
    {
        const int lane = tid & 31;
        const int warp = tid >> 5;
        const int p    = warp * 4 + (lane >> 3);   // 0..31
        const int tloc = lane & 7;
        float2* dst = g_xc + ((size_t)b * 32 + p) * T_LEN + t0;
        #pragma unroll
        for (int i = 0; i < 8; i++) {
            const int t = tloc + 8 * i;
            dst[t] = *(const float2*)&tile[t][2 * p];
        }
    }
}

// DFT-4 in place: (a,b,c,d) -> (X0,X1,X2,X3), W4 = exp(-2*pi*i/4) = -i
__device__ __forceinline__ void dft4(float2& a, float2& b, float2& c, float2& d)
{
    const float2 s02 = make_float2(a.x + c.x, a.y + c.y);
    const float2 d02 = make_float2(a.x - c.x, a.y - c.y);
    const float2 s13 = make_float2(b.x + d.x, b.y + d.y);
    const float2 d13 = make_float2(b.x - d.x, b.y - d.y);
    a = make_float2(s02.x + s13.x, s02.y + s13.y);
    b = make_float2(d02.x + d13.y, d02.y - d13.x);   // d02 - i*d13
    c = make_float2(s02.x - s13.x, s02.y - s13.y);
    d = make_float2(d02.x - d13.y, d02.y + d13.x);   // d02 + i*d13
}

// In-place DFT-16. Input natural order v[0..15]; output X[k1+4k2] lives in
// v[4k1+k2] (use PREG to fetch X[r]).
#define PREG(r) (4 * ((r) & 3) + ((r) >> 2))
__device__ __forceinline__ void dft16(float2 v[16])
{
    const float C1 = 0.92387953251128674f;   // cos(pi/8)
    const float S1 = 0.38268343236508978f;   // sin(pi/8)
    const float C2 = 0.70710678118654752f;   // cos(pi/4)

    #pragma unroll
    for (int t2 = 0; t2 < 4; t2++)
        dft4(v[t2], v[4 + t2], v[8 + t2], v[12 + t2]);

    v[5]  = cmul(v[5],  make_float2( C1, -S1));  // W^1
    v[6]  = cmul(v[6],  make_float2( C2, -C2));  // W^2
    v[7]  = cmul(v[7],  make_float2( S1, -C1));  // W^3
    v[9]  = cmul(v[9],  make_float2( C2, -C2));  // W^2
    v[10] = make_float2(v[10].y, -v[10].x);      // W^4 = -i
    v[11] = cmul(v[11], make_float2(-C2, -C2));  // W^6
    v[13] = cmul(v[13], make_float2( S1, -C1));  // W^3
    v[14] = cmul(v[14], make_float2(-C2, -C2));  // W^6
    v[15] = cmul(v[15], make_float2(-C1,  S1));  // W^9

    #pragma unroll
    for (int k1 = 0; k1 < 4; k1++)
        dft4(v[4 * k1], v[4 * k1 + 1], v[4 * k1 + 2], v[4 * k1 + 3]);
}

// Apply step twiddles v[r] *= w1^r using a log-depth power tree.
__device__ __forceinline__ void step_twiddle(float2 v[16], int m, float invNs16)
{
    const float ang = -6.283185307179586f * (float)m * invNs16;
    float s, c;
    sincosf(ang, &s, &c);
    const float2 w1 = make_float2(c, s);
    const float2 w2 = cmul(w1, w1);
    const float2 w4 = cmul(w2, w2);
    const float2 w8 = cmul(w4, w4);
    const float2 w3  = cmul(w2, w1);
    const float2 w5  = cmul(w4, w1);
    const float2 w6  = cmul(w4, w2);
    const float2 w7  = cmul(w4, w3);
    const float2 w9  = cmul(w8, w1);
    const float2 w10 = cmul(w8, w2);
    const float2 w11 = cmul(w8, w3);
    const float2 w12 = cmul(w8, w4);
    const float2 w13 = cmul(w8, w5);
    const float2 w14 = cmul(w8, w6);
    const float2 w15 = cmul(w8, w7);
    v[1]  = cmul(v[1],  w1);
    v[2]  = cmul(v[2],  w2);
    v[3]  = cmul(v[3],  w3);
    v[4]  = cmul(v[4],  w4);
    v[5]  = cmul(v[5],  w5);
    v[6]  = cmul(v[6],  w6);
    v[7]  = cmul(v[7],  w7);
    v[8]  = cmul(v[8],  w8);
    v[9]  = cmul(v[9],  w9);
    v[10] = cmul(v[10], w10);
    v[11] = cmul(v[11], w11);
    v[12] = cmul(v[12], w12);
    v[13] = cmul(v[13], w13);
    v[14] = cmul(v[14], w14);
    v[15] = cmul(v[15], w15);
}

// ---------------------------------------------------------------------------
// Kernel 1: packed complex FFT (2 real channels per FFT), radix-16 Stockham,
// natural-order output, + Hermitian unpack. Loads from g_xc (coalesced).
// grid = B*32 blocks, 256 threads. 32KB static smem.
// ---------------------------------------------------------------------------
__global__ __launch_bounds__(256) void fft_kernel()
{
    __shared__ float2 z[T_LEN];     // 32 KB, SWZ-indexed

    const int tid  = threadIdx.x;
    const float2* xcb = g_xc + (size_t)blockIdx.x * T_LEN;

    float2 v[16];

    // ---- Step 1 (Ns = 1): coalesced load, DFT16, store ----
    #pragma unroll
    for (int r = 0; r < 16; r++)
        v[r] = xcb[tid + 256 * r];
    dft16(v);
    {
        const int base = tid * 16;       // expand(j,1,16)
        #pragma unroll
        for (int r = 0; r < 16; r++)
            z[SWZ(base + r)] = v[PREG(r)];
    }
    __syncthreads();

    // ---- Step 2 (Ns = 16) ----
    #pragma unroll
    for (int r = 0; r < 16; r++)
        v[r] = z[SWZ(tid + 256 * r)];
    step_twiddle(v, tid & 15, 1.0f / 256.0f);
    dft16(v);
    __syncthreads();
    {
        const int base = (tid >> 4) * 256 + (tid & 15);   // expand(j,16,16)
        #pragma unroll
        for (int r = 0; r < 16; r++)
            z[SWZ(base + 16 * r)] = v[PREG(r)];
    }
    __syncthreads();

    // ---- Step 3 (Ns = 256) ----
    #pragma unroll
    for (int r = 0; r < 16; r++)
        v[r] = z[SWZ(tid + 256 * r)];
    step_twiddle(v, tid, 1.0f / 4096.0f);
    dft16(v);
    __syncthreads();
    {
        const int base = tid;            // expand(j,256,16) = j for j<256
        #pragma unroll
        for (int r = 0; r < 16; r++)
            z[SWZ(base + 256 * r)] = v[PREG(r)];
    }
    __syncthreads();

    // ---- Unpack Hermitian halves -> |X1[k]| + |X2[k]| for k in [0, 2048] ----
    float* out = g_part + (size_t)blockIdx.x * FPAD;
    for (int k = tid; k < NFREQ; k += 256) {
        const float2 a  = z[SWZ(k)];
        const float2 bm = z[SWZ((T_LEN - k) & (T_LEN - 1))];
        const float sr = 0.5f * (a.x + bm.x);
        const float si = 0.5f * (a.y - bm.y);
        const float dr = 0.5f * (a.x - bm.x);
        const float di = 0.5f * (a.y + bm.y);
        out[k] = sqrtf(sr * sr + si * si) + sqrtf(di * di + dr * dr);
    }
}

// ---------------------------------------------------------------------------
// Kernel 2: fused reduce + top-6 per batch. 1024 threads sum the 32
// channel-pair partials (fixed order, coalesced, 32-way MLP) into smem,
// then 6 shuffle-argmax rounds (value desc, smaller idx on tie). grid = B.
// ---------------------------------------------------------------------------
__global__ __launch_bounds__(1024) void redtopk_kernel()
{
    __shared__ float a[NFREQ];
    __shared__ float sv[32];
    __shared__ int   si[32];

    const int b    = blockIdx.x;
    const int tid  = threadIdx.x;
    const int lane = tid & 31;
    const int warp = tid >> 5;

    for (int k = tid; k < NFREQ; k += 1024) {
        float s = 0.0f;
        #pragma unroll 8
        for (int p = 0; p < 32; p++)
            s += g_part[(size_t)(b * 32 + p) * FPAD + k];
        a[k] = s;
    }
    __syncthreads();

    for (int sel = 0; sel < NCAND; sel++) {
        float bv = -1e30f;
        int   bi = 0x7fffffff;
        for (int k = tid; k < NFREQ; k += 1024) {
            const float v = a[k];
            if (v > bv) { bv = v; bi = k; }   // ascending scan -> smallest idx on tie
        }
        #pragma unroll
        for (int o = 16; o > 0; o >>= 1) {
            const float v2 = __shfl_xor_sync(0xffffffffu, bv, o);
            const int   i2 = __shfl_xor_sync(0xffffffffu, bi, o);
            argmax2(bv, bi, v2, i2);
        }
        if (lane == 0) { sv[warp] = bv; si[warp] = bi; }
        __syncthreads();
        if (warp == 0) {
            float v = sv[lane];
            int   i = si[lane];
            #pragma unroll
            for (int o = 16; o > 0; o >>= 1) {
                const float v2 = __shfl_xor_sync(0xffffffffu, v, o);
                const int   i2 = __shfl_xor_sync(0xffffffffu, i, o);
                argmax2(v, i, v2, i2);
            }
            if (lane == 0) {
                g_topidx[b * NCAND + sel] = i;
                a[i] = -1e30f;
            }
        }
        __syncthreads();
    }
}

// ---------------------------------------------------------------------------
// Kernel 3: fill r[b][j][t] for unique candidate periods. Reads g_xc
// (pair-major, t-contiguous): thread owns one t, loops 32 pairs, accumulates
// all candidates in registers -> zero shuffles, fully coalesced loads.
// grid = (16, B), 256 threads.
// ---------------------------------------------------------------------------
__global__ __launch_bounds__(256) void fill_kernel()
{
    const int b = blockIdx.y;
    const int t = blockIdx.x * 256 + threadIdx.x;

    int p[NCAND];
    bool uniq[NCAND];
    #pragma unroll
    for (int j = 0; j < NCAND; j++)
        p[j] = cand_period(g_topidx[b * NCAND + j]);
    #pragma unroll
    for (int j = 0; j < NCAND; j++) {
        bool u = true;
        #pragma unroll
        for (int k = 0; k < NCAND; k++)
            if (k < j && p[k] == p[j]) u = false;
        uniq[j] = u;
    }

    bool in[NCAND];
    #pragma unroll
    for (int j = 0; j < NCAND; j++)
        in[j] = (t + p[j] < T_LEN);

    const float2* xcb = g_xc + (size_t)b * 32 * T_LEN;

    float acc[NCAND];
    #pragma unroll
    for (int j = 0; j < NCAND; j++) acc[j] = 0.0f;

    #pragma unroll 4
    for (int pp = 0; pp < 32; pp++) {
        const float2* row = xcb + (size_t)pp * T_LEN;
        const float2 a = row[t];
        #pragma unroll
        for (int j = 0; j < NCAND; j++) {
            if (!uniq[j]) continue;
            if (in[j]) {
                const float2 bv = row[t + p[j]];
                acc[j] += a.x * bv.x + a.y * bv.y;
            }
        }
    }

    #pragma unroll
    for (int j = 0; j < NCAND; j++) {
        if (!uniq[j]) continue;
        g_r[(size_t)(b * NCAND + j) * T_LEN + t] = in[j] ? acc[j] : 0.0f;
    }
}

// ---------------------------------------------------------------------------
// Kernel 4: score per (batch, candidate) via PREFIX SUMS.
// grid = (NCAND, B). 256 threads. Reads r of the FIRST candidate with the
// same period (matches fill's dedup). All reductions fixed-order.
// ---------------------------------------------------------------------------
__global__ __launch_bounds__(256) void score_kernel()
{
    __shared__ float CR[T_LEN + 1];
    __shared__ float CQ[T_LEN + 1];
    __shared__ float wtot[8];
    __shared__ float woff_r[8];
    __shared__ float woff_q[8];
    __shared__ float red[256];

    const int j    = blockIdx.x;
    const int b    = blockIdx.y;
    const int tid  = threadIdx.x;
    const int lane = tid & 31;
    const int warp = tid >> 5;

    // period + dedup source index (first j' with equal period)
    int p = 0, jsrc = j;
    {
        int pj[NCAND];
        #pragma unroll
        for (int k = 0; k < NCAND; k++)
            pj[k] = cand_period(g_topidx[b * NCAND + k]);
        p = pj[j];
        #pragma unroll
        for (int k = NCAND - 1; k >= 0; k--)
            if (k <= j && pj[k] == p) jsrc = k;
    }

    const float* rs = g_r + (size_t)(b * NCAND + jsrc) * T_LEN;
    const float* qs = g_q + (size_t)b * T_LEN;

    // ---- Load 16 contiguous elements each, local inclusive scan ----
    const int base = tid * 16;
    float lr[16], lq[16];
    {
        float sr = 0.0f, sq = 0.0f;
        #pragma unroll
        for (int k = 0; k < 16; k++) {
            sr += rs[base + k]; lr[k] = sr;
            sq += qs[base + k]; lq[k] = sq;
        }
    }
    const float totr = lr[15], totq = lq[15];

    // ---- Scan the 256 per-thread totals (warp shuffle scan + warp offsets) ----
    float ir = totr, iq = totq;          // inclusive within warp
    #pragma unroll
    for (int o = 1; o < 32; o <<= 1) {
        const float vr = __shfl_up_sync(0xffffffffu, ir, o);
        const float vq = __shfl_up_sync(0xffffffffu, iq, o);
        if (lane >= o) { ir += vr; iq += vq; }
    }
    if (lane == 31) { wtot[warp] = ir; woff_q[warp] = iq; }  // warp totals (q via woff_q temp)
    __syncthreads();
    if (warp == 0 && lane == 0) {
        float ar = 0.0f, aq = 0.0f;
        #pragma unroll
        for (int w = 0; w < 8; w++) {
            const float tr = wtot[w], tq = woff_q[w];
            woff_r[w] = ar; woff_q[w] = aq;   // exclusive warp offsets
            ar += tr; aq += tq;
        }
    }
    __syncthreads();
    const float offr = woff_r[warp] + ir - totr;   // exclusive prefix for this thread
    const float offq = woff_q[warp] + iq - totq;

    // ---- Write inclusive scans to smem (CR[k] = sum of first k elements) ----
    if (tid == 0) { CR[0] = 0.0f; CQ[0] = 0.0f; }
    #pragma unroll
    for (int k = 0; k < 16; k++) {
        CR[base + k + 1] = offr + lr[k];
        CQ[base + k + 1] = offq + lq[k];
    }
    __syncthreads();

    // ---- Segment cosines, O(1) each ----
    const int nper = T_LEN / p;
    const int nseg = nper - 1;           // >= 1 since p <= T/2
    float wsum = 0.0f;
    for (int i = tid; i < nseg; i += 256) {
        const int s  = i * p;
        const int e  = s + p;
        const int e2 = e + p;            // <= nper*p <= T
        const float dots = CR[e] - CR[s];
        const float na = sqrtf(fmaxf(CQ[e]  - CQ[s], 0.0f));
        const float nb = sqrtf(fmaxf(CQ[e2] - CQ[e], 0.0f));
        wsum += dots / fmaxf(na * nb, 1e-8f);
    }

    // ---- Fixed-order block reduction ----
    red[tid] = wsum;
    __syncthreads();
    for (int s = 128; s > 0; s >>= 1) {
        if (tid < s) red[tid] += red[tid + s];
        __syncthreads();
    }
    if (tid == 0)
        g_scores[b * NCAND + j] = red[0] / (float)nseg;
}

// ---------------------------------------------------------------------------
// Kernel 5: final selection -> out = periods[64*3] ++ weights[64*3]
// ---------------------------------------------------------------------------
__global__ void select_kernel(float* __restrict__ out)
{
    const int b = blockIdx.x * blockDim.x + threadIdx.x;
    if (b >= B_SZ) return;

    int   pe[TOPK];
    float wt[TOPK];
    int cnt = 0;
    for (int j = 0; j < NCAND; j++) {
        const int idx = g_topidx[b * NCAND + j];
        const float pf  = 4096.0f / (float)(idx + 1);
        const float pfl = floorf(pf);
        const bool in_range     = (pf  >= 2.0f) && (pf  <= 2048.0f);
        const bool in_range_int = (pfl >= 2.0f) && (pfl <= 2048.0f);
        int pi = (int)pfl;
        pi = min(max(pi, 2), T_LEN / 2);
        const bool valid = in_range && in_range_int && (g_scores[b * NCAND + j] > 0.2f);
        if (valid && cnt < TOPK) { pe[cnt] = pi; wt[cnt] = 1.0f; cnt++; }
    }
    const int addp[3] = {1024, 1365, 2048};   // T//4, T//3, T//2 (int(T/1.5)=2730 > half)
    for (int j = cnt; j < TOPK; j++) {
        pe[j] = addp[min(j - cnt, 2)];
        wt[j] = 0.5f;
    }
    #pragma unroll
    for (int j = 0; j < TOPK; j++) {
        out[b * TOPK + j]                = (float)pe[j];
        out[B_SZ * TOPK + b * TOPK + j]  = wt[j];
    }
}

// ---------------------------------------------------------------------------
extern "C" void kernel_launch(void* const* d_in, const int* in_sizes, int n_in,
                              void* d_out, int out_size)
{
    const float* x  = (const float*)d_in[0];
    float* out = (float*)d_out;

    transpose_kernel<<<dim3(T_LEN / 64, B_SZ), 256>>>(x);
    fft_kernel<<<B_SZ * 32, 256>>>();
    redtopk_kernel<<<B_SZ, 1024>>>();
    fill_kernel<<<dim3(16, B_SZ), 256>>>();
    score_kernel<<<dim3(NCAND, B_SZ), 256>>>();
    select_kernel<<<1, 64>>>(out);
}